// round 10
// baseline (speedup 1.0000x reference)
#include <cuda_runtime.h>
#include <cuda_bf16.h>
#include <cstdint>

#define NEGC 1000000000000.0f
#define B_ 8
#define L_ 512
#define H_ 768
#define O_ 12
#define NN_ (O_*H_)   // 9216
#define ML_ (B_*L_)   // 4096
#define BK 64
#define NC (H_/BK)    // 12

// Scratch (__device__ globals per allocation rules)
__device__ __nv_bfloat16 g_Xb[(size_t)ML_*H_];
__device__ __nv_bfloat16 g_W1t[(size_t)NN_*H_];
__device__ __nv_bfloat16 g_Tb[(size_t)ML_*NN_];     // 75.5 MB bf16
__device__ float g_lini[ML_*O_];
__device__ float g_linj[ML_*O_];

__device__ __forceinline__ uint32_t swz(uint32_t off){ return off ^ ((off>>3)&0x70); }
__device__ __forceinline__ void cp16(uint32_t saddr, const void* g){
    asm volatile("cp.async.cg.shared.global [%0], [%1], 16;\n" :: "r"(saddr), "l"(g));
}

#define LDM4(d0,d1,d2,d3,addr) \
  asm volatile("ldmatrix.sync.aligned.m8n8.x4.shared.b16 {%0,%1,%2,%3}, [%4];\n" \
    : "=r"(d0),"=r"(d1),"=r"(d2),"=r"(d3) : "r"(addr))

#define MMA16816(c,a0,a1,a2,a3,b0,b1) \
  asm volatile("mma.sync.aligned.m16n8k16.row.col.f32.bf16.bf16.f32 " \
    "{%0,%1,%2,%3}, {%4,%5,%6,%7}, {%8,%9}, {%0,%1,%2,%3};\n" \
    : "+f"(c[0]),"+f"(c[1]),"+f"(c[2]),"+f"(c[3]) \
    : "r"(a0),"r"(a1),"r"(a2),"r"(a3),"r"(b0),"r"(b1))

// ---------------------------------------------------------------------------
// Fused: X -> bf16 (g_Xb)  +  lin_i / lin_j.  X read exactly once.
// ---------------------------------------------------------------------------
__global__ void lin_conv_kernel(const float* __restrict__ X, const float* __restrict__ W2){
    int warp = (blockIdx.x*blockDim.x + threadIdx.x) >> 5;
    int lane = threadIdx.x & 31;
    if (warp >= ML_) return;
    const float* xr = X + (size_t)warp*H_;
    __nv_bfloat16* xb = g_Xb + (size_t)warp*H_;
    float si[O_] = {}, sj[O_] = {};
    for (int k = lane; k < H_; k += 32){
        float xv = xr[k];
        xb[k] = __float2bfloat16_rn(xv);
        const float* wa = W2 + k*O_;
        const float* wb = W2 + (H_+k)*O_;
#pragma unroll
        for (int o = 0; o < O_; o++){
            si[o] = fmaf(xv, wa[o], si[o]);
            sj[o] = fmaf(xv, wb[o], sj[o]);
        }
    }
#pragma unroll
    for (int o = 0; o < O_; o++){
#pragma unroll
        for (int off = 16; off; off >>= 1){
            si[o] += __shfl_xor_sync(0xFFFFFFFFu, si[o], off);
            sj[o] += __shfl_xor_sync(0xFFFFFFFFu, sj[o], off);
        }
    }
    if (lane == 0){
#pragma unroll
        for (int o = 0; o < O_; o++){
            g_lini[warp*O_ + o] = si[o];
            g_linj[warp*O_ + o] = sj[o];
        }
    }
}

__global__ void conv_w1(const float* __restrict__ W1){
    __shared__ float t[32][33];
    int n0 = blockIdx.x*32, i0 = blockIdx.y*32;
    int tx = threadIdx.x, ty = threadIdx.y;        // (32, 8)
#pragma unroll
    for (int r = 0; r < 4; r++)
        t[ty+8*r][tx] = W1[(size_t)(i0+ty+8*r)*NN_ + n0+tx];
    __syncthreads();
#pragma unroll
    for (int r = 0; r < 4; r++)
        g_W1t[(size_t)(n0+ty+8*r)*H_ + i0+tx] = __float2bfloat16_rn(t[tx][ty+8*r]);
}

// ---------------------------------------------------------------------------
// STAGE 1: 128x256 block tile, 512 threads (16 warps x 32x64), 3-stage cp.async
// Tb[(b x)][(o j)] = Xb @ W1t^T   (M=4096, N=9216, K=768)
// ---------------------------------------------------------------------------
#define S1_STG 49152u

__device__ __forceinline__ void s1_fill(uint32_t sb, int stg,
    const __nv_bfloat16* Agl, const __nv_bfloat16* Bgl, int kt, int lr, int lc)
{
    uint32_t ab = sb + (uint32_t)stg*S1_STG, bb = ab + 16384u;
#pragma unroll
    for (int q = 0; q < 2; q++)
        cp16(ab + swz((lr+64*q)*128 + lc*16), Agl + (size_t)(64*q)*H_ + kt);
#pragma unroll
    for (int q = 0; q < 4; q++)
        cp16(bb + swz((lr+64*q)*128 + lc*16), Bgl + (size_t)(64*q)*H_ + kt);
    asm volatile("cp.async.commit_group;\n");
}

__global__ __launch_bounds__(512, 1) void s1_gemm()
{
    extern __shared__ __align__(1024) char smem[];
    uint32_t sb = (uint32_t)__cvta_generic_to_shared(smem);
    int tid = threadIdx.x, lane = tid & 31, warp = tid >> 5;
    int wm = warp & 3, wn = warp >> 2;             // 4x4 warps, 32x64 each

    int bm = blockIdx.y*128, bn = blockIdx.x*256;
    const __nv_bfloat16* Ag = g_Xb  + (size_t)bm*H_;
    const __nv_bfloat16* Bg = g_W1t + (size_t)bn*H_;
    int lr = tid >> 3, lc = tid & 7;               // loader: 64 rows x 8 chunks
    const __nv_bfloat16* Agl = Ag + (size_t)lr*H_ + lc*8;
    const __nv_bfloat16* Bgl = Bg + (size_t)lr*H_ + lc*8;

    float acc[2][8][4];
#pragma unroll
    for (int i=0;i<2;i++) for (int j=0;j<8;j++) for (int k=0;k<4;k++) acc[i][j][k]=0.f;

    s1_fill(sb, 0, Agl, Bgl, 0,  lr, lc);
    s1_fill(sb, 1, Agl, Bgl, BK, lr, lc);

    int rsel = lane & 15, hi = lane >> 4;
    for (int c = 0; c < NC; c++){
        if (c + 1 < NC) asm volatile("cp.async.wait_group 1;\n");
        else            asm volatile("cp.async.wait_group 0;\n");
        __syncthreads();

        uint32_t ab = sb + (uint32_t)(c % 3)*S1_STG, bb = ab + 16384u;
#pragma unroll
        for (int ks = 0; ks < 4; ks++){
            uint32_t a[2][4], bf[4][4];
#pragma unroll
            for (int mt = 0; mt < 2; mt++){
                uint32_t off = (wm*32 + mt*16 + rsel)*128 + ks*32 + hi*16;
                LDM4(a[mt][0],a[mt][1],a[mt][2],a[mt][3], ab + swz(off));
            }
#pragma unroll
            for (int p = 0; p < 4; p++){
                uint32_t off = (wn*64 + p*16 + rsel)*128 + ks*32 + hi*16;
                LDM4(bf[p][0],bf[p][1],bf[p][2],bf[p][3], bb + swz(off));
            }
#pragma unroll
            for (int mt = 0; mt < 2; mt++)
#pragma unroll
                for (int nt = 0; nt < 8; nt++)
                    MMA16816(acc[mt][nt], a[mt][0],a[mt][1],a[mt][2],a[mt][3],
                             bf[nt>>1][nt&1], bf[nt>>1][2+(nt&1)]);
        }
        if (c + 2 < NC)
            s1_fill(sb, (c + 2) % 3, Agl, Bgl, (c+2)*BK, lr, lc);
    }

    int g = lane >> 2, t2 = (lane & 3)*2;
#pragma unroll
    for (int mt = 0; mt < 2; mt++){
        int row = bm + wm*32 + mt*16 + g;
#pragma unroll
        for (int nt = 0; nt < 8; nt++){
            int col = bn + wn*64 + nt*8 + t2;
            *(__nv_bfloat162*)&g_Tb[(size_t)row*NN_ + col] =
                __floats2bfloat162_rn(acc[mt][nt][0], acc[mt][nt][1]);
            *(__nv_bfloat162*)&g_Tb[(size_t)(row+8)*NN_ + col] =
                __floats2bfloat162_rn(acc[mt][nt][2], acc[mt][nt][3]);
        }
    }
}

// ---------------------------------------------------------------------------
// STAGE 2 (round-6 proven config): 128x128, 256 threads, 2 CTA/SM, causal skip
// ---------------------------------------------------------------------------
#define S2_STG 32768u

__device__ __forceinline__ void s2_fill(uint32_t sb, int stg,
    const __nv_bfloat16* Agl, const __nv_bfloat16* Bgl, size_t lda, size_t ldb,
    int kt, int lr, int lc)
{
    uint32_t ab = sb + (uint32_t)stg*S2_STG, bb = ab + 16384u;
#pragma unroll
    for (int q = 0; q < 4; q++)
        cp16(ab + swz((lr+32*q)*128 + lc*16), Agl + (size_t)(32*q)*lda + kt);
#pragma unroll
    for (int q = 0; q < 4; q++)
        cp16(bb + swz((lr+32*q)*128 + lc*16), Bgl + (size_t)(32*q)*ldb + kt);
    asm volatile("cp.async.commit_group;\n");
}

__global__ __launch_bounds__(256, 2) void s2_gemm(
    const float* __restrict__ W2, const int* __restrict__ mask, float* __restrict__ out)
{
    extern __shared__ __align__(1024) char smem[];
    uint32_t sb = (uint32_t)__cvta_generic_to_shared(smem);
    int tid = threadIdx.x, lane = tid & 31, warp = tid >> 5;
    int wm = warp >> 1, wn = warp & 1;             // 4x2 warps, 32x64 each

    int bo = blockIdx.z;
    int b = bo / O_, o = bo % O_;
    int bm = blockIdx.y*128, bn = blockIdx.x*128;

    // Causal tile skip: whole tile y < x -> masks-only constants, no GEMM.
    if (bn + 128 <= bm){
        int r0 = tid >> 1;
        int cb = (tid & 1)*64;
        int x  = bm + r0;
        int mx = mask[b*L_ + x];
        const int* mrow = mask + b*L_ + bn + cb;
        float* orow = out + (size_t)bo*L_*L_ + (size_t)x*L_ + bn + cb;
#pragma unroll
        for (int j = 0; j < 64; j += 4){
            float4 v;
            v.x = (mx && mrow[j+0]) ? -NEGC : (-NEGC - NEGC);
            v.y = (mx && mrow[j+1]) ? -NEGC : (-NEGC - NEGC);
            v.z = (mx && mrow[j+2]) ? -NEGC : (-NEGC - NEGC);
            v.w = (mx && mrow[j+3]) ? -NEGC : (-NEGC - NEGC);
            *(float4*)&orow[j] = v;
        }
        return;
    }

    const __nv_bfloat16* Ag = g_Tb + (size_t)(b*L_+bm)*NN_ + o*H_;
    const __nv_bfloat16* Bg = g_Xb + (size_t)(b*L_+bn)*H_;
    size_t lda = NN_, ldb = H_;
    int lr = tid >> 3, lc = tid & 7;
    const __nv_bfloat16* Agl = Ag + (size_t)lr*lda + lc*8;
    const __nv_bfloat16* Bgl = Bg + (size_t)lr*ldb + lc*8;

    float acc[2][8][4];
#pragma unroll
    for (int i=0;i<2;i++) for (int j=0;j<8;j++) for (int k=0;k<4;k++) acc[i][j][k]=0.f;

    s2_fill(sb, 0, Agl, Bgl, lda, ldb, 0,  lr, lc);
    s2_fill(sb, 1, Agl, Bgl, lda, ldb, BK, lr, lc);

    int rsel = lane & 15, hi = lane >> 4;
    for (int c = 0; c < NC; c++){
        if (c + 1 < NC) asm volatile("cp.async.wait_group 1;\n");
        else            asm volatile("cp.async.wait_group 0;\n");
        __syncthreads();

        uint32_t ab = sb + (uint32_t)(c % 3)*S2_STG, bb = ab + 16384u;
#pragma unroll
        for (int ks = 0; ks < 4; ks++){
            uint32_t a[2][4], bf[4][4];
#pragma unroll
            for (int mt = 0; mt < 2; mt++){
                uint32_t off = (wm*32 + mt*16 + rsel)*128 + ks*32 + hi*16;
                LDM4(a[mt][0],a[mt][1],a[mt][2],a[mt][3], ab + swz(off));
            }
#pragma unroll
            for (int p = 0; p < 4; p++){
                uint32_t off = (wn*64 + p*16 + rsel)*128 + ks*32 + hi*16;
                LDM4(bf[p][0],bf[p][1],bf[p][2],bf[p][3], bb + swz(off));
            }
#pragma unroll
            for (int mt = 0; mt < 2; mt++)
#pragma unroll
                for (int nt = 0; nt < 8; nt++)
                    MMA16816(acc[mt][nt], a[mt][0],a[mt][1],a[mt][2],a[mt][3],
                             bf[nt>>1][nt&1], bf[nt>>1][2+(nt&1)]);
        }
        if (c + 2 < NC)
            s2_fill(sb, (c + 2) % 3, Agl, Bgl, lda, ldb, (c+2)*BK, lr, lc);
    }

    int g = lane >> 2, t2 = (lane & 3)*2;
    float bias = W2[2*H_*O_ + o];
    int myv[16]; float lj[16];
#pragma unroll
    for (int nt = 0; nt < 8; nt++){
        int y = bn + wn*64 + nt*8 + t2;
        myv[2*nt]   = mask[b*L_+y];
        myv[2*nt+1] = mask[b*L_+y+1];
        lj[2*nt]    = g_linj[(b*L_+y)*O_+o];
        lj[2*nt+1]  = g_linj[(b*L_+y+1)*O_+o];
    }
#pragma unroll
    for (int mt = 0; mt < 2; mt++)
#pragma unroll
        for (int half = 0; half < 2; half++){
            int x  = bm + wm*32 + mt*16 + g + half*8;
            int mx = mask[b*L_+x];
            float li = g_lini[(b*L_+x)*O_+o] + bias;
            float* orow = out + (size_t)bo*L_*L_ + (size_t)x*L_;
#pragma unroll
            for (int nt = 0; nt < 8; nt++){
                int y = bn + wn*64 + nt*8 + t2;
                float v0 = acc[mt][nt][half*2+0] + li + lj[2*nt];
                float v1 = acc[mt][nt][half*2+1] + li + lj[2*nt+1];
                if (!mx)         { v0 = -NEGC; v1 = -NEGC; }
                if (!myv[2*nt])    v0 = -NEGC;
                if (!myv[2*nt+1])  v1 = -NEGC;
                if (y   < x)       v0 -= NEGC;
                if (y+1 < x)       v1 -= NEGC;
                *(float2*)&orow[y] = make_float2(v0, v1);
            }
        }
}

// ---------------------------------------------------------------------------
extern "C" void kernel_launch(void* const* d_in, const int* in_sizes, int n_in,
                              void* d_out, int out_size) {
    const float* inputs = nullptr;
    const float* w1 = nullptr;
    const float* w2 = nullptr;
    const int*   mask = nullptr;
    for (int i = 0; i < n_in; i++) {
        if      (in_sizes[i] == B_*L_*H_)      inputs = (const float*)d_in[i];
        else if (in_sizes[i] == H_*O_*H_)      w1     = (const float*)d_in[i];
        else if (in_sizes[i] == (2*H_+1)*O_)   w2     = (const float*)d_in[i];
        else if (in_sizes[i] == B_*L_)         mask   = (const int*)d_in[i];
    }
    float* out = (float*)d_out;

    cudaFuncSetAttribute(s1_gemm, cudaFuncAttributeMaxDynamicSharedMemorySize, 3*S1_STG);
    cudaFuncSetAttribute(s2_gemm, cudaFuncAttributeMaxDynamicSharedMemorySize, 3*S2_STG);

    lin_conv_kernel<<<ML_/8, 256>>>(inputs, w2);
    conv_w1<<<dim3(NN_/32, H_/32), dim3(32,8)>>>(w1);
    s1_gemm<<<dim3(NN_/256, ML_/128), 512, 3*S1_STG>>>();
    s2_gemm<<<dim3(L_/128, L_/128, B_*O_), 256, 3*S2_STG>>>(w2, mask, out);
}

// round 11
// speedup vs baseline: 1.0098x; 1.0098x over previous
#include <cuda_runtime.h>
#include <cuda_bf16.h>
#include <cstdint>

#define NEGC 1000000000000.0f
#define B_ 8
#define L_ 512
#define H_ 768
#define O_ 12
#define NN_ (O_*H_)   // 9216
#define ML_ (B_*L_)   // 4096
#define BK 64
#define NC (H_/BK)    // 12
#define STG 32768u

// Scratch (__device__ globals per allocation rules)
__device__ __nv_bfloat16 g_Xb[(size_t)ML_*H_];   // all rows (stage-2 B side)
__device__ __nv_bfloat16 g_Xc[(size_t)ML_*H_];   // compacted unmasked rows per batch
__device__ __nv_bfloat16 g_W1t[(size_t)NN_*H_];
__device__ __nv_bfloat16 g_Tb[(size_t)ML_*NN_];  // compacted T rows
__device__ float g_lini[ML_*O_];
__device__ float g_linj[ML_*O_];
__device__ int g_cnt[B_];
__device__ int g_rowidx[ML_];                    // b*L+x -> compacted global row

__device__ __forceinline__ uint32_t swz(uint32_t off){ return off ^ ((off>>3)&0x70); }
__device__ __forceinline__ void cp16(uint32_t saddr, const void* g){
    asm volatile("cp.async.cg.shared.global [%0], [%1], 16;\n" :: "r"(saddr), "l"(g));
}

#define LDM4(d0,d1,d2,d3,addr) \
  asm volatile("ldmatrix.sync.aligned.m8n8.x4.shared.b16 {%0,%1,%2,%3}, [%4];\n" \
    : "=r"(d0),"=r"(d1),"=r"(d2),"=r"(d3) : "r"(addr))

#define MMA16816(c,a0,a1,a2,a3,b0,b1) \
  asm volatile("mma.sync.aligned.m16n8k16.row.col.f32.bf16.bf16.f32 " \
    "{%0,%1,%2,%3}, {%4,%5,%6,%7}, {%8,%9}, {%0,%1,%2,%3};\n" \
    : "+f"(c[0]),"+f"(c[1]),"+f"(c[2]),"+f"(c[3]) \
    : "r"(a0),"r"(a1),"r"(a2),"r"(a3),"r"(b0),"r"(b1))

// ---------------------------------------------------------------------------
// Fused: X -> bf16 (g_Xb) + lin_i / lin_j.  X read exactly once here.
// ---------------------------------------------------------------------------
__global__ void lin_conv_kernel(const float* __restrict__ X, const float* __restrict__ W2){
    int warp = (blockIdx.x*blockDim.x + threadIdx.x) >> 5;
    int lane = threadIdx.x & 31;
    if (warp >= ML_) return;
    const float* xr = X + (size_t)warp*H_;
    __nv_bfloat16* xb = g_Xb + (size_t)warp*H_;
    float si[O_] = {}, sj[O_] = {};
    for (int k = lane; k < H_; k += 32){
        float xv = xr[k];
        xb[k] = __float2bfloat16_rn(xv);
        const float* wa = W2 + k*O_;
        const float* wb = W2 + (H_+k)*O_;
#pragma unroll
        for (int o = 0; o < O_; o++){
            si[o] = fmaf(xv, wa[o], si[o]);
            sj[o] = fmaf(xv, wb[o], sj[o]);
        }
    }
#pragma unroll
    for (int o = 0; o < O_; o++){
#pragma unroll
        for (int off = 16; off; off >>= 1){
            si[o] += __shfl_xor_sync(0xFFFFFFFFu, si[o], off);
            sj[o] += __shfl_xor_sync(0xFFFFFFFFu, sj[o], off);
        }
    }
    if (lane == 0){
#pragma unroll
        for (int o = 0; o < O_; o++){
            g_lini[warp*O_ + o] = si[o];
            g_linj[warp*O_ + o] = sj[o];
        }
    }
}

__global__ void conv_w1(const float* __restrict__ W1){
    __shared__ float t[32][33];
    int n0 = blockIdx.x*32, i0 = blockIdx.y*32;
    int tx = threadIdx.x, ty = threadIdx.y;        // (32, 8)
#pragma unroll
    for (int r = 0; r < 4; r++)
        t[ty+8*r][tx] = W1[(size_t)(i0+ty+8*r)*NN_ + n0+tx];
    __syncthreads();
#pragma unroll
    for (int r = 0; r < 4; r++)
        g_W1t[(size_t)(n0+ty+8*r)*H_ + i0+tx] = __float2bfloat16_rn(t[tx][ty+8*r]);
}

// ---------------------------------------------------------------------------
// Mask compaction: per batch, prefix-sum mask; rowidx; gather unmasked X rows
// (fp32 -> bf16) into g_Xc.  One block of 512 threads per batch.
// ---------------------------------------------------------------------------
__global__ void compact_kernel(const float* __restrict__ X, const int* __restrict__ mask){
    __shared__ int wsum[16];
    __shared__ short sgx[L_];
    __shared__ int scnt;
    int b = blockIdx.x, tid = threadIdx.x, lane = tid & 31, w = tid >> 5;
    int m = mask[b*L_ + tid];
    unsigned bal = __ballot_sync(0xFFFFFFFFu, m);
    int wpre = __popc(bal & ((1u << lane) - 1));
    if (lane == 31) wsum[w] = __popc(bal);
    __syncthreads();
    if (tid == 0){
        int s = 0;
#pragma unroll
        for (int i = 0; i < 16; i++){ int t = wsum[i]; wsum[i] = s; s += t; }
        scnt = s;
        g_cnt[b] = s;
    }
    __syncthreads();
    int pos = wsum[w] + wpre;
    g_rowidx[b*L_ + tid] = b*L_ + (m ? pos : 0);
    if (m) sgx[pos] = (short)tid;
    __syncthreads();
    int cnt = scnt;
    for (int j = w; j < cnt; j += 16){
        int x = sgx[j];
        const float* src = X + (size_t)(b*L_ + x)*H_;
        __nv_bfloat16* dst = g_Xc + (size_t)(b*L_ + j)*H_;
        for (int k = lane; k < H_/2; k += 32){
            float2 v = ((const float2*)src)[k];
            ((__nv_bfloat162*)dst)[k] = __floats2bfloat162_rn(v.x, v.y);
        }
    }
}

// ---------------------------------------------------------------------------
// STAGE 1: Tb[compacted row][(o j)] = Xc @ W1t^T, 128x128, 256 thr, 2 CTA/SM.
// Blocks past cnt[b] exit. Rows >= cnt compute garbage (finite, never read).
// ---------------------------------------------------------------------------
__device__ __forceinline__ void s1_fill(uint32_t sb, int stg,
    const __nv_bfloat16* Agl, const __nv_bfloat16* Bgl, int kt, int lr, int lc)
{
    uint32_t ab = sb + (uint32_t)stg*STG, bb = ab + 16384u;
#pragma unroll
    for (int q = 0; q < 4; q++)
        cp16(ab + swz((lr+32*q)*128 + lc*16), Agl + (size_t)(32*q)*H_ + kt);
#pragma unroll
    for (int q = 0; q < 4; q++)
        cp16(bb + swz((lr+32*q)*128 + lc*16), Bgl + (size_t)(32*q)*H_ + kt);
    asm volatile("cp.async.commit_group;\n");
}

__global__ __launch_bounds__(256, 2) void s1_gemm()
{
    extern __shared__ __align__(1024) char smem[];
    uint32_t sb = (uint32_t)__cvta_generic_to_shared(smem);
    int tid = threadIdx.x, lane = tid & 31, warp = tid >> 5;
    int wm = warp >> 1, wn = warp & 1;             // 4x2 warps, 32x64 each

    int bm = blockIdx.y*128, bn = blockIdx.x*128;
    int b = bm >> 9, local = bm & 511;
    if (local >= g_cnt[b]) return;                 // compacted slab exhausted

    const __nv_bfloat16* Ag = g_Xc  + (size_t)bm*H_;
    const __nv_bfloat16* Bg = g_W1t + (size_t)bn*H_;
    int lr = tid >> 3, lc = tid & 7;
    const __nv_bfloat16* Agl = Ag + (size_t)lr*H_ + lc*8;
    const __nv_bfloat16* Bgl = Bg + (size_t)lr*H_ + lc*8;

    float acc[2][8][4];
#pragma unroll
    for (int i=0;i<2;i++) for (int j=0;j<8;j++) for (int k=0;k<4;k++) acc[i][j][k]=0.f;

    s1_fill(sb, 0, Agl, Bgl, 0,  lr, lc);
    s1_fill(sb, 1, Agl, Bgl, BK, lr, lc);

    int rsel = lane & 15, hi = lane >> 4;
    for (int c = 0; c < NC; c++){
        if (c + 1 < NC) asm volatile("cp.async.wait_group 1;\n");
        else            asm volatile("cp.async.wait_group 0;\n");
        __syncthreads();
        uint32_t ab = sb + (uint32_t)(c % 3)*STG, bb = ab + 16384u;
#pragma unroll
        for (int ks = 0; ks < 4; ks++){
            uint32_t a[2][4], bf[4][4];
#pragma unroll
            for (int mt = 0; mt < 2; mt++){
                uint32_t off = (wm*32 + mt*16 + rsel)*128 + ks*32 + hi*16;
                LDM4(a[mt][0],a[mt][1],a[mt][2],a[mt][3], ab + swz(off));
            }
#pragma unroll
            for (int p = 0; p < 4; p++){
                uint32_t off = (wn*64 + p*16 + rsel)*128 + ks*32 + hi*16;
                LDM4(bf[p][0],bf[p][1],bf[p][2],bf[p][3], bb + swz(off));
            }
#pragma unroll
            for (int mt = 0; mt < 2; mt++)
#pragma unroll
                for (int nt = 0; nt < 8; nt++)
                    MMA16816(acc[mt][nt], a[mt][0],a[mt][1],a[mt][2],a[mt][3],
                             bf[nt>>1][nt&1], bf[nt>>1][2+(nt&1)]);
        }
        if (c + 2 < NC)
            s1_fill(sb, (c + 2) % 3, Agl, Bgl, (c+2)*BK, lr, lc);
    }

    int g = lane >> 2, t2 = (lane & 3)*2;
#pragma unroll
    for (int mt = 0; mt < 2; mt++){
        int row = bm + wm*32 + mt*16 + g;
#pragma unroll
        for (int nt = 0; nt < 8; nt++){
            int col = bn + wn*64 + nt*8 + t2;
            *(__nv_bfloat162*)&g_Tb[(size_t)row*NN_ + col] =
                __floats2bfloat162_rn(acc[mt][nt][0], acc[mt][nt][1]);
            *(__nv_bfloat162*)&g_Tb[(size_t)(row+8)*NN_ + col] =
                __floats2bfloat162_rn(acc[mt][nt][2], acc[mt][nt][3]);
        }
    }
}

// ---------------------------------------------------------------------------
// STAGE 2: per (b,o) C[x][y] = T[rowidx[x]] @ Xb[y]^T + fused epilogue.
// Masked x rows read dummy row (forced constant in epilogue). Causal skip.
// ---------------------------------------------------------------------------
__device__ __forceinline__ void s2_fill(uint32_t sb, int stg,
    const __nv_bfloat16* const* Ar, const __nv_bfloat16* Bgl, int kt, int lr, int lc)
{
    uint32_t ab = sb + (uint32_t)stg*STG, bb = ab + 16384u;
#pragma unroll
    for (int q = 0; q < 4; q++)
        cp16(ab + swz((lr+32*q)*128 + lc*16), Ar[q] + kt);
#pragma unroll
    for (int q = 0; q < 4; q++)
        cp16(bb + swz((lr+32*q)*128 + lc*16), Bgl + (size_t)(32*q)*H_ + kt);
    asm volatile("cp.async.commit_group;\n");
}

__global__ __launch_bounds__(256, 2) void s2_gemm(
    const float* __restrict__ W2, const int* __restrict__ mask, float* __restrict__ out)
{
    extern __shared__ __align__(1024) char smem[];
    uint32_t sb = (uint32_t)__cvta_generic_to_shared(smem);
    int tid = threadIdx.x, lane = tid & 31, warp = tid >> 5;
    int wm = warp >> 1, wn = warp & 1;

    int bo = blockIdx.z;
    int b = bo / O_, o = bo % O_;
    int bm = blockIdx.y*128, bn = blockIdx.x*128;

    if (bn + 128 <= bm){   // fully-causal tile: constants only
        int r0 = tid >> 1;
        int cb = (tid & 1)*64;
        int x  = bm + r0;
        int mx = mask[b*L_ + x];
        const int* mrow = mask + b*L_ + bn + cb;
        float* orow = out + (size_t)bo*L_*L_ + (size_t)x*L_ + bn + cb;
#pragma unroll
        for (int j = 0; j < 64; j += 4){
            float4 v;
            v.x = (mx && mrow[j+0]) ? -NEGC : (-NEGC - NEGC);
            v.y = (mx && mrow[j+1]) ? -NEGC : (-NEGC - NEGC);
            v.z = (mx && mrow[j+2]) ? -NEGC : (-NEGC - NEGC);
            v.w = (mx && mrow[j+3]) ? -NEGC : (-NEGC - NEGC);
            *(float4*)&orow[j] = v;
        }
        return;
    }

    int lr = tid >> 3, lc = tid & 7;
    const __nv_bfloat16* Ar[4];
#pragma unroll
    for (int q = 0; q < 4; q++){
        int gr = g_rowidx[b*L_ + bm + lr + 32*q];
        Ar[q] = g_Tb + (size_t)gr*NN_ + o*H_ + lc*8;
    }
    const __nv_bfloat16* Bgl = g_Xb + (size_t)(b*L_ + bn + lr)*H_ + lc*8;

    float acc[2][8][4];
#pragma unroll
    for (int i=0;i<2;i++) for (int j=0;j<8;j++) for (int k=0;k<4;k++) acc[i][j][k]=0.f;

    s2_fill(sb, 0, Ar, Bgl, 0,  lr, lc);
    s2_fill(sb, 1, Ar, Bgl, BK, lr, lc);

    int rsel = lane & 15, hi = lane >> 4;
    for (int c = 0; c < NC; c++){
        if (c + 1 < NC) asm volatile("cp.async.wait_group 1;\n");
        else            asm volatile("cp.async.wait_group 0;\n");
        __syncthreads();
        uint32_t ab = sb + (uint32_t)(c % 3)*STG, bb = ab + 16384u;
#pragma unroll
        for (int ks = 0; ks < 4; ks++){
            uint32_t a[2][4], bf[4][4];
#pragma unroll
            for (int mt = 0; mt < 2; mt++){
                uint32_t off = (wm*32 + mt*16 + rsel)*128 + ks*32 + hi*16;
                LDM4(a[mt][0],a[mt][1],a[mt][2],a[mt][3], ab + swz(off));
            }
#pragma unroll
            for (int p = 0; p < 4; p++){
                uint32_t off = (wn*64 + p*16 + rsel)*128 + ks*32 + hi*16;
                LDM4(bf[p][0],bf[p][1],bf[p][2],bf[p][3], bb + swz(off));
            }
#pragma unroll
            for (int mt = 0; mt < 2; mt++)
#pragma unroll
                for (int nt = 0; nt < 8; nt++)
                    MMA16816(acc[mt][nt], a[mt][0],a[mt][1],a[mt][2],a[mt][3],
                             bf[nt>>1][nt&1], bf[nt>>1][2+(nt&1)]);
        }
        if (c + 2 < NC)
            s2_fill(sb, (c + 2) % 3, Ar, Bgl, (c+2)*BK, lr, lc);
    }

    int g = lane >> 2, t2 = (lane & 3)*2;
    float bias = W2[2*H_*O_ + o];
    int myv[16]; float lj[16];
#pragma unroll
    for (int nt = 0; nt < 8; nt++){
        int y = bn + wn*64 + nt*8 + t2;
        myv[2*nt]   = mask[b*L_+y];
        myv[2*nt+1] = mask[b*L_+y+1];
        lj[2*nt]    = g_linj[(b*L_+y)*O_+o];
        lj[2*nt+1]  = g_linj[(b*L_+y+1)*O_+o];
    }
#pragma unroll
    for (int mt = 0; mt < 2; mt++)
#pragma unroll
        for (int half = 0; half < 2; half++){
            int x  = bm + wm*32 + mt*16 + g + half*8;
            int mx = mask[b*L_+x];
            float li = g_lini[(b*L_+x)*O_+o] + bias;
            float* orow = out + (size_t)bo*L_*L_ + (size_t)x*L_;
#pragma unroll
            for (int nt = 0; nt < 8; nt++){
                int y = bn + wn*64 + nt*8 + t2;
                float v0 = acc[mt][nt][half*2+0] + li + lj[2*nt];
                float v1 = acc[mt][nt][half*2+1] + li + lj[2*nt+1];
                if (!mx)         { v0 = -NEGC; v1 = -NEGC; }
                if (!myv[2*nt])    v0 = -NEGC;
                if (!myv[2*nt+1])  v1 = -NEGC;
                if (y   < x)       v0 -= NEGC;
                if (y+1 < x)       v1 -= NEGC;
                *(float2*)&orow[y] = make_float2(v0, v1);
            }
        }
}

// ---------------------------------------------------------------------------
extern "C" void kernel_launch(void* const* d_in, const int* in_sizes, int n_in,
                              void* d_out, int out_size) {
    const float* inputs = nullptr;
    const float* w1 = nullptr;
    const float* w2 = nullptr;
    const int*   mask = nullptr;
    for (int i = 0; i < n_in; i++) {
        if      (in_sizes[i] == B_*L_*H_)      inputs = (const float*)d_in[i];
        else if (in_sizes[i] == H_*O_*H_)      w1     = (const float*)d_in[i];
        else if (in_sizes[i] == (2*H_+1)*O_)   w2     = (const float*)d_in[i];
        else if (in_sizes[i] == B_*L_)         mask   = (const int*)d_in[i];
    }
    float* out = (float*)d_out;

    cudaFuncSetAttribute(s1_gemm, cudaFuncAttributeMaxDynamicSharedMemorySize, 3*STG);
    cudaFuncSetAttribute(s2_gemm, cudaFuncAttributeMaxDynamicSharedMemorySize, 3*STG);

    lin_conv_kernel<<<ML_/8, 256>>>(inputs, w2);
    conv_w1<<<dim3(NN_/32, H_/32), dim3(32,8)>>>(w1);
    compact_kernel<<<B_, 512>>>(inputs, mask);
    s1_gemm<<<dim3(NN_/128, ML_/128), 256, 3*STG>>>();
    s2_gemm<<<dim3(L_/128, L_/128, B_*O_), 256, 3*STG>>>(w2, mask, out);
}

// round 12
// speedup vs baseline: 1.2596x; 1.2473x over previous
#include <cuda_runtime.h>
#include <cuda_bf16.h>
#include <cstdint>

#define NEGC 1000000000000.0f
#define B_ 8
#define L_ 512
#define H_ 768
#define O_ 12
#define NN_ (O_*H_)   // 9216
#define ML_ (B_*L_)   // 4096
#define BK 64
#define NC (H_/BK)    // 12
#define STG 32768u
#define SM_TOTAL (3*STG + 1024)

// Scratch (__device__ globals per allocation rules)
__device__ __nv_bfloat16 g_Xb[(size_t)ML_*H_];   // all rows (stage-2 B side)
__device__ __nv_bfloat16 g_Xc[(size_t)ML_*H_];   // compacted unmasked rows per batch
__device__ __nv_bfloat16 g_W1t[(size_t)NN_*H_];
__device__ __nv_bfloat16 g_Tb[(size_t)ML_*NN_];  // compacted T rows
__device__ float g_lini[ML_*O_];
__device__ float g_linj[ML_*O_];
__device__ int g_cnt[B_];
__device__ int g_sgx[ML_];                       // b*L+j (compacted) -> original x

__device__ __forceinline__ uint32_t swz(uint32_t off){ return off ^ ((off>>3)&0x70); }
__device__ __forceinline__ void cp16(uint32_t saddr, const void* g){
    asm volatile("cp.async.cg.shared.global [%0], [%1], 16;\n" :: "r"(saddr), "l"(g));
}

#define LDM4(d0,d1,d2,d3,addr) \
  asm volatile("ldmatrix.sync.aligned.m8n8.x4.shared.b16 {%0,%1,%2,%3}, [%4];\n" \
    : "=r"(d0),"=r"(d1),"=r"(d2),"=r"(d3) : "r"(addr))

#define MMA16816(c,a0,a1,a2,a3,b0,b1) \
  asm volatile("mma.sync.aligned.m16n8k16.row.col.f32.bf16.bf16.f32 " \
    "{%0,%1,%2,%3}, {%4,%5,%6,%7}, {%8,%9}, {%0,%1,%2,%3};\n" \
    : "+f"(c[0]),"+f"(c[1]),"+f"(c[2]),"+f"(c[3]) \
    : "r"(a0),"r"(a1),"r"(a2),"r"(a3),"r"(b0),"r"(b1))

// ---------------------------------------------------------------------------
__global__ void lin_conv_kernel(const float* __restrict__ X, const float* __restrict__ W2){
    int warp = (blockIdx.x*blockDim.x + threadIdx.x) >> 5;
    int lane = threadIdx.x & 31;
    if (warp >= ML_) return;
    const float* xr = X + (size_t)warp*H_;
    __nv_bfloat16* xb = g_Xb + (size_t)warp*H_;
    float si[O_] = {}, sj[O_] = {};
    for (int k = lane; k < H_; k += 32){
        float xv = xr[k];
        xb[k] = __float2bfloat16_rn(xv);
        const float* wa = W2 + k*O_;
        const float* wb = W2 + (H_+k)*O_;
#pragma unroll
        for (int o = 0; o < O_; o++){
            si[o] = fmaf(xv, wa[o], si[o]);
            sj[o] = fmaf(xv, wb[o], sj[o]);
        }
    }
#pragma unroll
    for (int o = 0; o < O_; o++){
#pragma unroll
        for (int off = 16; off; off >>= 1){
            si[o] += __shfl_xor_sync(0xFFFFFFFFu, si[o], off);
            sj[o] += __shfl_xor_sync(0xFFFFFFFFu, sj[o], off);
        }
    }
    if (lane == 0){
#pragma unroll
        for (int o = 0; o < O_; o++){
            g_lini[warp*O_ + o] = si[o];
            g_linj[warp*O_ + o] = sj[o];
        }
    }
}

__global__ void conv_w1(const float* __restrict__ W1){
    __shared__ float t[32][33];
    int n0 = blockIdx.x*32, i0 = blockIdx.y*32;
    int tx = threadIdx.x, ty = threadIdx.y;        // (32, 8)
#pragma unroll
    for (int r = 0; r < 4; r++)
        t[ty+8*r][tx] = W1[(size_t)(i0+ty+8*r)*NN_ + n0+tx];
    __syncthreads();
#pragma unroll
    for (int r = 0; r < 4; r++)
        g_W1t[(size_t)(n0+ty+8*r)*H_ + i0+tx] = __float2bfloat16_rn(t[tx][ty+8*r]);
}

// ---------------------------------------------------------------------------
// Compaction phase A: per batch, prefix-sum mask -> cnt, sgx. 8 blocks, cheap.
// ---------------------------------------------------------------------------
__global__ void scan_kernel(const int* __restrict__ mask){
    __shared__ int wsum[16];
    int b = blockIdx.x, tid = threadIdx.x, lane = tid & 31, w = tid >> 5;
    int m = mask[b*L_ + tid];
    unsigned bal = __ballot_sync(0xFFFFFFFFu, m);
    int wpre = __popc(bal & ((1u << lane) - 1));
    if (lane == 31) wsum[w] = __popc(bal);
    __syncthreads();
    if (tid == 0){
        int s = 0;
#pragma unroll
        for (int i = 0; i < 16; i++){ int t = wsum[i]; wsum[i] = s; s += t; }
        g_cnt[b] = s;
    }
    __syncthreads();
    if (m) g_sgx[b*L_ + wsum[w] + wpre] = tid;
}

// Gather: grid (32, B_), 256 thr. Block handles compacted rows [bx*16, bx*16+16).
__global__ void gather_kernel(const float* __restrict__ X){
    int b = blockIdx.y;
    int cnt = g_cnt[b];
    int j0 = blockIdx.x*16;
    int lane = threadIdx.x & 31, w = threadIdx.x >> 5;
#pragma unroll
    for (int it = 0; it < 2; it++){
        int j = j0 + it*8 + w;
        if (j >= cnt) continue;
        int x = g_sgx[b*L_ + j];
        const float* src = X + (size_t)(b*L_ + x)*H_;
        __nv_bfloat16* dst = g_Xc + (size_t)(b*L_ + j)*H_;
        for (int k = lane; k < H_/2; k += 32){
            float2 v = ((const float2*)src)[k];
            ((__nv_bfloat162*)dst)[k] = __floats2bfloat162_rn(v.x, v.y);
        }
    }
}

// Masked-x rows are pure constants: y<x ? -2e12 : -1e12, for all o.
__global__ void fill_masked(const int* __restrict__ mask, float* __restrict__ out){
    int row = blockIdx.x;
    int b = row >> 9, x = row & 511;
    if (mask[row]) return;
    int t = threadIdx.x;                 // 128 threads, 4 y each
    float4 v;
    int y0 = t*4;
    v.x = (y0+0 < x) ? (-NEGC - NEGC) : -NEGC;
    v.y = (y0+1 < x) ? (-NEGC - NEGC) : -NEGC;
    v.z = (y0+2 < x) ? (-NEGC - NEGC) : -NEGC;
    v.w = (y0+3 < x) ? (-NEGC - NEGC) : -NEGC;
#pragma unroll
    for (int o = 0; o < O_; o++)
        *(float4*)&out[((size_t)(b*O_+o)*L_ + x)*L_ + y0] = v;
}

// ---------------------------------------------------------------------------
// STAGE 1: Tb[compacted][(o j)] = Xc @ W1t^T, 128x128, 256 thr, 2 CTA/SM.
// ---------------------------------------------------------------------------
__device__ __forceinline__ void s1_fill(uint32_t sb, int stg,
    const __nv_bfloat16* Agl, const __nv_bfloat16* Bgl, int kt, int lr, int lc)
{
    uint32_t ab = sb + (uint32_t)stg*STG, bb = ab + 16384u;
#pragma unroll
    for (int q = 0; q < 4; q++)
        cp16(ab + swz((lr+32*q)*128 + lc*16), Agl + (size_t)(32*q)*H_ + kt);
#pragma unroll
    for (int q = 0; q < 4; q++)
        cp16(bb + swz((lr+32*q)*128 + lc*16), Bgl + (size_t)(32*q)*H_ + kt);
    asm volatile("cp.async.commit_group;\n");
}

__global__ __launch_bounds__(256, 2) void s1_gemm()
{
    extern __shared__ __align__(1024) char smem[];
    uint32_t sb = (uint32_t)__cvta_generic_to_shared(smem);
    int tid = threadIdx.x, lane = tid & 31, warp = tid >> 5;
    int wm = warp >> 1, wn = warp & 1;

    int bm = blockIdx.y*128, bn = blockIdx.x*128;
    int b = bm >> 9, local = bm & 511;
    if (local >= g_cnt[b]) return;

    const __nv_bfloat16* Ag = g_Xc  + (size_t)bm*H_;
    const __nv_bfloat16* Bg = g_W1t + (size_t)bn*H_;
    int lr = tid >> 3, lc = tid & 7;
    const __nv_bfloat16* Agl = Ag + (size_t)lr*H_ + lc*8;
    const __nv_bfloat16* Bgl = Bg + (size_t)lr*H_ + lc*8;

    float acc[2][8][4];
#pragma unroll
    for (int i=0;i<2;i++) for (int j=0;j<8;j++) for (int k=0;k<4;k++) acc[i][j][k]=0.f;

    s1_fill(sb, 0, Agl, Bgl, 0,  lr, lc);
    s1_fill(sb, 1, Agl, Bgl, BK, lr, lc);

    int rsel = lane & 15, hi = lane >> 4;
    for (int c = 0; c < NC; c++){
        if (c + 1 < NC) asm volatile("cp.async.wait_group 1;\n");
        else            asm volatile("cp.async.wait_group 0;\n");
        __syncthreads();
        uint32_t ab = sb + (uint32_t)(c % 3)*STG, bb = ab + 16384u;
#pragma unroll
        for (int ks = 0; ks < 4; ks++){
            uint32_t a[2][4], bf[4][4];
#pragma unroll
            for (int mt = 0; mt < 2; mt++){
                uint32_t off = (wm*32 + mt*16 + rsel)*128 + ks*32 + hi*16;
                LDM4(a[mt][0],a[mt][1],a[mt][2],a[mt][3], ab + swz(off));
            }
#pragma unroll
            for (int p = 0; p < 4; p++){
                uint32_t off = (wn*64 + p*16 + rsel)*128 + ks*32 + hi*16;
                LDM4(bf[p][0],bf[p][1],bf[p][2],bf[p][3], bb + swz(off));
            }
#pragma unroll
            for (int mt = 0; mt < 2; mt++)
#pragma unroll
                for (int nt = 0; nt < 8; nt++)
                    MMA16816(acc[mt][nt], a[mt][0],a[mt][1],a[mt][2],a[mt][3],
                             bf[nt>>1][nt&1], bf[nt>>1][2+(nt&1)]);
        }
        if (c + 2 < NC)
            s1_fill(sb, (c + 2) % 3, Agl, Bgl, (c+2)*BK, lr, lc);
    }

    int g = lane >> 2, t2 = (lane & 3)*2;
#pragma unroll
    for (int mt = 0; mt < 2; mt++){
        int row = bm + wm*32 + mt*16 + g;
#pragma unroll
        for (int nt = 0; nt < 8; nt++){
            int col = bn + wn*64 + nt*8 + t2;
            *(__nv_bfloat162*)&g_Tb[(size_t)row*NN_ + col] =
                __floats2bfloat162_rn(acc[mt][nt][0], acc[mt][nt][1]);
            *(__nv_bfloat162*)&g_Tb[(size_t)(row+8)*NN_ + col] =
                __floats2bfloat162_rn(acc[mt][nt][2], acc[mt][nt][3]);
        }
    }
}

// ---------------------------------------------------------------------------
// STAGE 2 (row-compacted): per (b,o) slab of 128 compacted rows vs 128 y cols.
// A side sequential from g_Tb; output rows scattered to x=sgx[r].
// ---------------------------------------------------------------------------
__device__ __forceinline__ void s2_fill(uint32_t sb, int stg,
    const __nv_bfloat16* Agl, const __nv_bfloat16* Bgl, int kt, int lr, int lc)
{
    uint32_t ab = sb + (uint32_t)stg*STG, bb = ab + 16384u;
#pragma unroll
    for (int q = 0; q < 4; q++)
        cp16(ab + swz((lr+32*q)*128 + lc*16), Agl + (size_t)(32*q)*NN_ + kt);
#pragma unroll
    for (int q = 0; q < 4; q++)
        cp16(bb + swz((lr+32*q)*128 + lc*16), Bgl + (size_t)(32*q)*H_ + kt);
    asm volatile("cp.async.commit_group;\n");
}

__global__ __launch_bounds__(256, 2) void s2_gemm(
    const float* __restrict__ W2, const int* __restrict__ mask, float* __restrict__ out)
{
    extern __shared__ __align__(1024) char smem[];
    uint32_t sb = (uint32_t)__cvta_generic_to_shared(smem);
    int tid = threadIdx.x, lane = tid & 31, warp = tid >> 5;
    int wm = warp >> 1, wn = warp & 1;

    int bo = blockIdx.z;
    int b = bo / O_, o = bo % O_;
    int bm = blockIdx.y*128, bn = blockIdx.x*128;   // bm = compacted row slab
    int cnt = g_cnt[b];
    if (bm >= cnt) return;                          // masked rows: fill_masked covers
    int nrow = min(128, cnt - bm);
    int x_min = g_sgx[b*L_ + bm];

    size_t outbase = (size_t)bo*L_*L_;

    // Fully-causal tile (y_max < x_min for all rows): constants, no GEMM.
    if (bn + 128 <= x_min){
        for (int r = tid >> 1; r < nrow; r += 128){
            int x  = g_sgx[b*L_ + bm + r];
            int cb = (tid & 1)*64;
            const int* mrow = mask + b*L_ + bn + cb;
            float* orow = out + outbase + (size_t)x*L_ + bn + cb;
#pragma unroll
            for (int j = 0; j < 64; j += 4){
                float4 v;
                v.x = mrow[j+0] ? -NEGC : (-NEGC - NEGC);
                v.y = mrow[j+1] ? -NEGC : (-NEGC - NEGC);
                v.z = mrow[j+2] ? -NEGC : (-NEGC - NEGC);
                v.w = mrow[j+3] ? -NEGC : (-NEGC - NEGC);
                *(float4*)&orow[j] = v;
            }
        }
        return;
    }

    // s_sgx for epilogue scatter
    int* s_sgx = (int*)(smem + 3*STG);
    if (tid < 128)
        s_sgx[tid] = (tid < nrow) ? g_sgx[b*L_ + bm + tid] : -1;

    const __nv_bfloat16* Ag = g_Tb + (size_t)bm*NN_ + o*H_;
    const __nv_bfloat16* Bg = g_Xb + (size_t)(b*L_ + bn)*H_;
    int lr = tid >> 3, lc = tid & 7;
    const __nv_bfloat16* Agl = Ag + (size_t)lr*NN_ + lc*8;
    const __nv_bfloat16* Bgl = Bg + (size_t)lr*H_ + lc*8;

    float acc[2][8][4];
#pragma unroll
    for (int i=0;i<2;i++) for (int j=0;j<8;j++) for (int k=0;k<4;k++) acc[i][j][k]=0.f;

    s2_fill(sb, 0, Agl, Bgl, 0,  lr, lc);
    s2_fill(sb, 1, Agl, Bgl, BK, lr, lc);

    int rsel = lane & 15, hi = lane >> 4;
    for (int c = 0; c < NC; c++){
        if (c + 1 < NC) asm volatile("cp.async.wait_group 1;\n");
        else            asm volatile("cp.async.wait_group 0;\n");
        __syncthreads();
        uint32_t ab = sb + (uint32_t)(c % 3)*STG, bb = ab + 16384u;
#pragma unroll
        for (int ks = 0; ks < 4; ks++){
            uint32_t a[2][4], bf[4][4];
#pragma unroll
            for (int mt = 0; mt < 2; mt++){
                uint32_t off = (wm*32 + mt*16 + rsel)*128 + ks*32 + hi*16;
                LDM4(a[mt][0],a[mt][1],a[mt][2],a[mt][3], ab + swz(off));
            }
#pragma unroll
            for (int p = 0; p < 4; p++){
                uint32_t off = (wn*64 + p*16 + rsel)*128 + ks*32 + hi*16;
                LDM4(bf[p][0],bf[p][1],bf[p][2],bf[p][3], bb + swz(off));
            }
#pragma unroll
            for (int mt = 0; mt < 2; mt++)
#pragma unroll
                for (int nt = 0; nt < 8; nt++)
                    MMA16816(acc[mt][nt], a[mt][0],a[mt][1],a[mt][2],a[mt][3],
                             bf[nt>>1][nt&1], bf[nt>>1][2+(nt&1)]);
        }
        if (c + 2 < NC)
            s2_fill(sb, (c + 2) % 3, Agl, Bgl, (c+2)*BK, lr, lc);
    }

    int g = lane >> 2, t2 = (lane & 3)*2;
    float bias = W2[2*H_*O_ + o];
    int myv[16]; float lj[16];
#pragma unroll
    for (int nt = 0; nt < 8; nt++){
        int y = bn + wn*64 + nt*8 + t2;
        myv[2*nt]   = mask[b*L_+y];
        myv[2*nt+1] = mask[b*L_+y+1];
        lj[2*nt]    = g_linj[(b*L_+y)*O_+o];
        lj[2*nt+1]  = g_linj[(b*L_+y+1)*O_+o];
    }
#pragma unroll
    for (int mt = 0; mt < 2; mt++)
#pragma unroll
        for (int half = 0; half < 2; half++){
            int rloc = wm*32 + mt*16 + g + half*8;
            int x = s_sgx[rloc];
            if (x < 0) continue;
            float li = g_lini[(b*L_+x)*O_+o] + bias;
            float* orow = out + outbase + (size_t)x*L_;
#pragma unroll
            for (int nt = 0; nt < 8; nt++){
                int y = bn + wn*64 + nt*8 + t2;
                float v0 = acc[mt][nt][half*2+0] + li + lj[2*nt];
                float v1 = acc[mt][nt][half*2+1] + li + lj[2*nt+1];
                if (!myv[2*nt])    v0 = -NEGC;
                if (!myv[2*nt+1])  v1 = -NEGC;
                if (y   < x)       v0 -= NEGC;
                if (y+1 < x)       v1 -= NEGC;
                *(float2*)&orow[y] = make_float2(v0, v1);
            }
        }
}

// ---------------------------------------------------------------------------
extern "C" void kernel_launch(void* const* d_in, const int* in_sizes, int n_in,
                              void* d_out, int out_size) {
    const float* inputs = nullptr;
    const float* w1 = nullptr;
    const float* w2 = nullptr;
    const int*   mask = nullptr;
    for (int i = 0; i < n_in; i++) {
        if      (in_sizes[i] == B_*L_*H_)      inputs = (const float*)d_in[i];
        else if (in_sizes[i] == H_*O_*H_)      w1     = (const float*)d_in[i];
        else if (in_sizes[i] == (2*H_+1)*O_)   w2     = (const float*)d_in[i];
        else if (in_sizes[i] == B_*L_)         mask   = (const int*)d_in[i];
    }
    float* out = (float*)d_out;

    cudaFuncSetAttribute(s1_gemm, cudaFuncAttributeMaxDynamicSharedMemorySize, SM_TOTAL);
    cudaFuncSetAttribute(s2_gemm, cudaFuncAttributeMaxDynamicSharedMemorySize, SM_TOTAL);

    scan_kernel<<<B_, 512>>>(mask);
    lin_conv_kernel<<<ML_/8, 256>>>(inputs, w2);
    conv_w1<<<dim3(NN_/32, H_/32), dim3(32,8)>>>(w1);
    gather_kernel<<<dim3(32, B_), 256>>>(inputs);
    fill_masked<<<ML_, 128>>>(mask, out);
    s1_gemm<<<dim3(NN_/128, ML_/128), 256, SM_TOTAL>>>();
    s2_gemm<<<dim3(L_/128, L_/128, B_*O_), 256, SM_TOTAL>>>(w2, mask, out);
}

// round 13
// speedup vs baseline: 1.3632x; 1.0822x over previous
#include <cuda_runtime.h>
#include <cuda_bf16.h>
#include <cstdint>

#define NEGC 1000000000000.0f
#define B_ 8
#define L_ 512
#define H_ 768
#define O_ 12
#define NN_ (O_*H_)   // 9216
#define ML_ (B_*L_)   // 4096
#define BK 64
#define NC (H_/BK)    // 12
#define STG 32768u
#define SM_TOTAL (3*STG + 1024)

// Scratch (__device__ globals per allocation rules)
__device__ __nv_bfloat16 g_Xb[(size_t)ML_*H_];   // all rows (stage-2 B side)
__device__ __nv_bfloat16 g_Xc[(size_t)ML_*H_];   // globally compacted unmasked rows
__device__ __nv_bfloat16 g_W1t[(size_t)NN_*H_];
__device__ __nv_bfloat16 g_Tb[(size_t)ML_*NN_];  // compacted T rows
__device__ float g_lini[ML_*O_];
__device__ float g_linj[ML_*O_];
__device__ int g_cnt[B_];
__device__ int g_off[B_ + 1];                    // exclusive scan of cnt; g_off[B_]=tot
__device__ int g_sgx[ML_];                       // b*L+j (compacted, per-batch) -> original x

__device__ __forceinline__ uint32_t swz(uint32_t off){ return off ^ ((off>>3)&0x70); }
__device__ __forceinline__ void cp16(uint32_t saddr, const void* g){
    asm volatile("cp.async.cg.shared.global [%0], [%1], 16;\n" :: "r"(saddr), "l"(g));
}

#define LDM4(d0,d1,d2,d3,addr) \
  asm volatile("ldmatrix.sync.aligned.m8n8.x4.shared.b16 {%0,%1,%2,%3}, [%4];\n" \
    : "=r"(d0),"=r"(d1),"=r"(d2),"=r"(d3) : "r"(addr))

#define MMA16816(c,a0,a1,a2,a3,b0,b1) \
  asm volatile("mma.sync.aligned.m16n8k16.row.col.f32.bf16.bf16.f32 " \
    "{%0,%1,%2,%3}, {%4,%5,%6,%7}, {%8,%9}, {%0,%1,%2,%3};\n" \
    : "+f"(c[0]),"+f"(c[1]),"+f"(c[2]),"+f"(c[3]) \
    : "r"(a0),"r"(a1),"r"(a2),"r"(a3),"r"(b0),"r"(b1))

// ---------------------------------------------------------------------------
__global__ void lin_conv_kernel(const float* __restrict__ X, const float* __restrict__ W2){
    int warp = (blockIdx.x*blockDim.x + threadIdx.x) >> 5;
    int lane = threadIdx.x & 31;
    if (warp >= ML_) return;
    const float* xr = X + (size_t)warp*H_;
    __nv_bfloat16* xb = g_Xb + (size_t)warp*H_;
    float si[O_] = {}, sj[O_] = {};
    for (int k = lane; k < H_; k += 32){
        float xv = xr[k];
        xb[k] = __float2bfloat16_rn(xv);
        const float* wa = W2 + k*O_;
        const float* wb = W2 + (H_+k)*O_;
#pragma unroll
        for (int o = 0; o < O_; o++){
            si[o] = fmaf(xv, wa[o], si[o]);
            sj[o] = fmaf(xv, wb[o], sj[o]);
        }
    }
#pragma unroll
    for (int o = 0; o < O_; o++){
#pragma unroll
        for (int off = 16; off; off >>= 1){
            si[o] += __shfl_xor_sync(0xFFFFFFFFu, si[o], off);
            sj[o] += __shfl_xor_sync(0xFFFFFFFFu, sj[o], off);
        }
    }
    if (lane == 0){
#pragma unroll
        for (int o = 0; o < O_; o++){
            g_lini[warp*O_ + o] = si[o];
            g_linj[warp*O_ + o] = sj[o];
        }
    }
}

__global__ void conv_w1(const float* __restrict__ W1){
    __shared__ float t[32][33];
    int n0 = blockIdx.x*32, i0 = blockIdx.y*32;
    int tx = threadIdx.x, ty = threadIdx.y;        // (32, 8)
#pragma unroll
    for (int r = 0; r < 4; r++)
        t[ty+8*r][tx] = W1[(size_t)(i0+ty+8*r)*NN_ + n0+tx];
    __syncthreads();
#pragma unroll
    for (int r = 0; r < 4; r++)
        g_W1t[(size_t)(n0+ty+8*r)*H_ + i0+tx] = __float2bfloat16_rn(t[tx][ty+8*r]);
}

// ---------------------------------------------------------------------------
// Compaction: per-batch prefix-sum -> cnt, sgx;  then batch-offset scan.
// ---------------------------------------------------------------------------
__global__ void scan_kernel(const int* __restrict__ mask){
    __shared__ int wsum[16];
    int b = blockIdx.x, tid = threadIdx.x, lane = tid & 31, w = tid >> 5;
    int m = mask[b*L_ + tid];
    unsigned bal = __ballot_sync(0xFFFFFFFFu, m);
    int wpre = __popc(bal & ((1u << lane) - 1));
    if (lane == 31) wsum[w] = __popc(bal);
    __syncthreads();
    if (tid == 0){
        int s = 0;
#pragma unroll
        for (int i = 0; i < 16; i++){ int t = wsum[i]; wsum[i] = s; s += t; }
        g_cnt[b] = s;
    }
    __syncthreads();
    if (m) g_sgx[b*L_ + wsum[w] + wpre] = tid;
}

__global__ void offs_kernel(){
    int s = 0;
#pragma unroll
    for (int b = 0; b < B_; b++){ g_off[b] = s; s += g_cnt[b]; }
    g_off[B_] = s;
}

// Gather: grid (32, B_), 256 thr. Writes batch rows at global offset.
__global__ void gather_kernel(const float* __restrict__ X){
    int b = blockIdx.y;
    int cnt = g_cnt[b];
    int off = g_off[b];
    int j0 = blockIdx.x*16;
    int lane = threadIdx.x & 31, w = threadIdx.x >> 5;
#pragma unroll
    for (int it = 0; it < 2; it++){
        int j = j0 + it*8 + w;
        if (j >= cnt) continue;
        int x = g_sgx[b*L_ + j];
        const float* src = X + (size_t)(b*L_ + x)*H_;
        __nv_bfloat16* dst = g_Xc + (size_t)(off + j)*H_;
        for (int k = lane; k < H_/2; k += 32){
            float2 v = ((const float2*)src)[k];
            ((__nv_bfloat162*)dst)[k] = __floats2bfloat162_rn(v.x, v.y);
        }
    }
}

// Masked-x rows are pure constants: y<x ? -2e12 : -1e12, for all o.
__global__ void fill_masked(const int* __restrict__ mask, float* __restrict__ out){
    int row = blockIdx.x;
    int b = row >> 9, x = row & 511;
    if (mask[row]) return;
    int t = threadIdx.x;                 // 128 threads, 4 y each
    float4 v;
    int y0 = t*4;
    v.x = (y0+0 < x) ? (-NEGC - NEGC) : -NEGC;
    v.y = (y0+1 < x) ? (-NEGC - NEGC) : -NEGC;
    v.z = (y0+2 < x) ? (-NEGC - NEGC) : -NEGC;
    v.w = (y0+3 < x) ? (-NEGC - NEGC) : -NEGC;
#pragma unroll
    for (int o = 0; o < O_; o++)
        *(float4*)&out[((size_t)(b*O_+o)*L_ + x)*L_ + y0] = v;
}

// ---------------------------------------------------------------------------
// STAGE 1: Tb[global compacted][(o j)] = Xc @ W1t^T. Dense grid over tot rows.
// ---------------------------------------------------------------------------
__device__ __forceinline__ void s1_fill(uint32_t sb, int stg,
    const __nv_bfloat16* Agl, const __nv_bfloat16* Bgl, int kt, int lr, int lc)
{
    uint32_t ab = sb + (uint32_t)stg*STG, bb = ab + 16384u;
#pragma unroll
    for (int q = 0; q < 4; q++)
        cp16(ab + swz((lr+32*q)*128 + lc*16), Agl + (size_t)(32*q)*H_ + kt);
#pragma unroll
    for (int q = 0; q < 4; q++)
        cp16(bb + swz((lr+32*q)*128 + lc*16), Bgl + (size_t)(32*q)*H_ + kt);
    asm volatile("cp.async.commit_group;\n");
}

__global__ __launch_bounds__(256, 2) void s1_gemm()
{
    extern __shared__ __align__(1024) char smem[];
    uint32_t sb = (uint32_t)__cvta_generic_to_shared(smem);
    int tid = threadIdx.x, lane = tid & 31, warp = tid >> 5;
    int wm = warp >> 1, wn = warp & 1;

    int bm = blockIdx.y*128, bn = blockIdx.x*128;
    if (bm >= g_off[B_]) return;                   // beyond total compacted rows

    const __nv_bfloat16* Ag = g_Xc  + (size_t)bm*H_;
    const __nv_bfloat16* Bg = g_W1t + (size_t)bn*H_;
    int lr = tid >> 3, lc = tid & 7;
    const __nv_bfloat16* Agl = Ag + (size_t)lr*H_ + lc*8;
    const __nv_bfloat16* Bgl = Bg + (size_t)lr*H_ + lc*8;

    float acc[2][8][4];
#pragma unroll
    for (int i=0;i<2;i++) for (int j=0;j<8;j++) for (int k=0;k<4;k++) acc[i][j][k]=0.f;

    s1_fill(sb, 0, Agl, Bgl, 0,  lr, lc);
    s1_fill(sb, 1, Agl, Bgl, BK, lr, lc);

    int rsel = lane & 15, hi = lane >> 4;
    for (int c = 0; c < NC; c++){
        if (c + 1 < NC) asm volatile("cp.async.wait_group 1;\n");
        else            asm volatile("cp.async.wait_group 0;\n");
        __syncthreads();
        uint32_t ab = sb + (uint32_t)(c % 3)*STG, bb = ab + 16384u;
#pragma unroll
        for (int ks = 0; ks < 4; ks++){
            uint32_t a[2][4], bf[4][4];
#pragma unroll
            for (int mt = 0; mt < 2; mt++){
                uint32_t off = (wm*32 + mt*16 + rsel)*128 + ks*32 + hi*16;
                LDM4(a[mt][0],a[mt][1],a[mt][2],a[mt][3], ab + swz(off));
            }
#pragma unroll
            for (int p = 0; p < 4; p++){
                uint32_t off = (wn*64 + p*16 + rsel)*128 + ks*32 + hi*16;
                LDM4(bf[p][0],bf[p][1],bf[p][2],bf[p][3], bb + swz(off));
            }
#pragma unroll
            for (int mt = 0; mt < 2; mt++)
#pragma unroll
                for (int nt = 0; nt < 8; nt++)
                    MMA16816(acc[mt][nt], a[mt][0],a[mt][1],a[mt][2],a[mt][3],
                             bf[nt>>1][nt&1], bf[nt>>1][2+(nt&1)]);
        }
        if (c + 2 < NC)
            s1_fill(sb, (c + 2) % 3, Agl, Bgl, (c+2)*BK, lr, lc);
    }

    int g = lane >> 2, t2 = (lane & 3)*2;
#pragma unroll
    for (int mt = 0; mt < 2; mt++){
        int row = bm + wm*32 + mt*16 + g;
#pragma unroll
        for (int nt = 0; nt < 8; nt++){
            int col = bn + wn*64 + nt*8 + t2;
            *(__nv_bfloat162*)&g_Tb[(size_t)row*NN_ + col] =
                __floats2bfloat162_rn(acc[mt][nt][0], acc[mt][nt][1]);
            *(__nv_bfloat162*)&g_Tb[(size_t)(row+8)*NN_ + col] =
                __floats2bfloat162_rn(acc[mt][nt][2], acc[mt][nt][3]);
        }
    }
}

// ---------------------------------------------------------------------------
// STAGE 2 (row-compacted): per (b,o) slab of 128 compacted rows vs 128 y cols.
// A side sequential from g_Tb at off[b]+bm; output rows scattered to x=sgx[r].
// ---------------------------------------------------------------------------
__device__ __forceinline__ void s2_fill(uint32_t sb, int stg,
    const __nv_bfloat16* Agl, const __nv_bfloat16* Bgl, int kt, int lr, int lc)
{
    uint32_t ab = sb + (uint32_t)stg*STG, bb = ab + 16384u;
#pragma unroll
    for (int q = 0; q < 4; q++)
        cp16(ab + swz((lr+32*q)*128 + lc*16), Agl + (size_t)(32*q)*NN_ + kt);
#pragma unroll
    for (int q = 0; q < 4; q++)
        cp16(bb + swz((lr+32*q)*128 + lc*16), Bgl + (size_t)(32*q)*H_ + kt);
    asm volatile("cp.async.commit_group;\n");
}

__global__ __launch_bounds__(256, 2) void s2_gemm(
    const float* __restrict__ W2, const int* __restrict__ mask, float* __restrict__ out)
{
    extern __shared__ __align__(1024) char smem[];
    uint32_t sb = (uint32_t)__cvta_generic_to_shared(smem);
    int tid = threadIdx.x, lane = tid & 31, warp = tid >> 5;
    int wm = warp >> 1, wn = warp & 1;

    int bo = blockIdx.z;
    int b = bo / O_, o = bo % O_;
    int bm = blockIdx.y*128, bn = blockIdx.x*128;   // bm = per-batch compacted slab
    int cnt = g_cnt[b];
    if (bm >= cnt) return;
    int nrow = min(128, cnt - bm);
    int x_min = g_sgx[b*L_ + bm];

    size_t outbase = (size_t)bo*L_*L_;

    // Fully-causal tile (y_max < x_min for all rows): constants, no GEMM.
    if (bn + 128 <= x_min){
        for (int r = tid >> 1; r < nrow; r += 128){
            int x  = g_sgx[b*L_ + bm + r];
            int cb = (tid & 1)*64;
            const int* mrow = mask + b*L_ + bn + cb;
            float* orow = out + outbase + (size_t)x*L_ + bn + cb;
#pragma unroll
            for (int j = 0; j < 64; j += 4){
                float4 v;
                v.x = mrow[j+0] ? -NEGC : (-NEGC - NEGC);
                v.y = mrow[j+1] ? -NEGC : (-NEGC - NEGC);
                v.z = mrow[j+2] ? -NEGC : (-NEGC - NEGC);
                v.w = mrow[j+3] ? -NEGC : (-NEGC - NEGC);
                *(float4*)&orow[j] = v;
            }
        }
        return;
    }

    int* s_sgx = (int*)(smem + 3*STG);
    if (tid < 128)
        s_sgx[tid] = (tid < nrow) ? g_sgx[b*L_ + bm + tid] : -1;

    const __nv_bfloat16* Ag = g_Tb + (size_t)(g_off[b] + bm)*NN_ + o*H_;
    const __nv_bfloat16* Bg = g_Xb + (size_t)(b*L_ + bn)*H_;
    int lr = tid >> 3, lc = tid & 7;
    const __nv_bfloat16* Agl = Ag + (size_t)lr*NN_ + lc*8;
    const __nv_bfloat16* Bgl = Bg + (size_t)lr*H_ + lc*8;

    float acc[2][8][4];
#pragma unroll
    for (int i=0;i<2;i++) for (int j=0;j<8;j++) for (int k=0;k<4;k++) acc[i][j][k]=0.f;

    s2_fill(sb, 0, Agl, Bgl, 0,  lr, lc);
    s2_fill(sb, 1, Agl, Bgl, BK, lr, lc);

    int rsel = lane & 15, hi = lane >> 4;
    for (int c = 0; c < NC; c++){
        if (c + 1 < NC) asm volatile("cp.async.wait_group 1;\n");
        else            asm volatile("cp.async.wait_group 0;\n");
        __syncthreads();
        uint32_t ab = sb + (uint32_t)(c % 3)*STG, bb = ab + 16384u;
#pragma unroll
        for (int ks = 0; ks < 4; ks++){
            uint32_t a[2][4], bf[4][4];
#pragma unroll
            for (int mt = 0; mt < 2; mt++){
                uint32_t off = (wm*32 + mt*16 + rsel)*128 + ks*32 + hi*16;
                LDM4(a[mt][0],a[mt][1],a[mt][2],a[mt][3], ab + swz(off));
            }
#pragma unroll
            for (int p = 0; p < 4; p++){
                uint32_t off = (wn*64 + p*16 + rsel)*128 + ks*32 + hi*16;
                LDM4(bf[p][0],bf[p][1],bf[p][2],bf[p][3], bb + swz(off));
            }
#pragma unroll
            for (int mt = 0; mt < 2; mt++)
#pragma unroll
                for (int nt = 0; nt < 8; nt++)
                    MMA16816(acc[mt][nt], a[mt][0],a[mt][1],a[mt][2],a[mt][3],
                             bf[nt>>1][nt&1], bf[nt>>1][2+(nt&1)]);
        }
        if (c + 2 < NC)
            s2_fill(sb, (c + 2) % 3, Agl, Bgl, (c+2)*BK, lr, lc);
    }

    int g = lane >> 2, t2 = (lane & 3)*2;
    float bias = W2[2*H_*O_ + o];
    int myv[16]; float lj[16];
#pragma unroll
    for (int nt = 0; nt < 8; nt++){
        int y = bn + wn*64 + nt*8 + t2;
        myv[2*nt]   = mask[b*L_+y];
        myv[2*nt+1] = mask[b*L_+y+1];
        lj[2*nt]    = g_linj[(b*L_+y)*O_+o];
        lj[2*nt+1]  = g_linj[(b*L_+y+1)*O_+o];
    }
#pragma unroll
    for (int mt = 0; mt < 2; mt++)
#pragma unroll
        for (int half = 0; half < 2; half++){
            int rloc = wm*32 + mt*16 + g + half*8;
            int x = s_sgx[rloc];
            if (x < 0) continue;
            float li = g_lini[(b*L_+x)*O_+o] + bias;
            float* orow = out + outbase + (size_t)x*L_;
#pragma unroll
            for (int nt = 0; nt < 8; nt++){
                int y = bn + wn*64 + nt*8 + t2;
                float v0 = acc[mt][nt][half*2+0] + li + lj[2*nt];
                float v1 = acc[mt][nt][half*2+1] + li + lj[2*nt+1];
                if (!myv[2*nt])    v0 = -NEGC;
                if (!myv[2*nt+1])  v1 = -NEGC;
                if (y   < x)       v0 -= NEGC;
                if (y+1 < x)       v1 -= NEGC;
                *(float2*)&orow[y] = make_float2(v0, v1);
            }
        }
}

// ---------------------------------------------------------------------------
extern "C" void kernel_launch(void* const* d_in, const int* in_sizes, int n_in,
                              void* d_out, int out_size) {
    const float* inputs = nullptr;
    const float* w1 = nullptr;
    const float* w2 = nullptr;
    const int*   mask = nullptr;
    for (int i = 0; i < n_in; i++) {
        if      (in_sizes[i] == B_*L_*H_)      inputs = (const float*)d_in[i];
        else if (in_sizes[i] == H_*O_*H_)      w1     = (const float*)d_in[i];
        else if (in_sizes[i] == (2*H_+1)*O_)   w2     = (const float*)d_in[i];
        else if (in_sizes[i] == B_*L_)         mask   = (const int*)d_in[i];
    }
    float* out = (float*)d_out;

    cudaFuncSetAttribute(s1_gemm, cudaFuncAttributeMaxDynamicSharedMemorySize, SM_TOTAL);
    cudaFuncSetAttribute(s2_gemm, cudaFuncAttributeMaxDynamicSharedMemorySize, SM_TOTAL);

    scan_kernel<<<B_, 512>>>(mask);
    offs_kernel<<<1, 1>>>();
    lin_conv_kernel<<<ML_/8, 256>>>(inputs, w2);
    conv_w1<<<dim3(NN_/32, H_/32), dim3(32,8)>>>(w1);
    gather_kernel<<<dim3(32, B_), 256>>>(inputs);
    fill_masked<<<ML_, 128>>>(mask, out);
    s1_gemm<<<dim3(NN_/128, ML_/128), 256, SM_TOTAL>>>();
    s2_gemm<<<dim3(L_/128, L_/128, B_*O_), 256, SM_TOTAL>>>(w2, mask, out);
}

// round 15
// speedup vs baseline: 1.6490x; 1.2097x over previous
#include <cuda_runtime.h>
#include <cuda_bf16.h>
#include <cstdint>

#define NEGC 1000000000000.0f
#define B_ 8
#define L_ 512
#define H_ 768
#define O_ 12
#define NN_ (O_*H_)   // 9216
#define NT_ (NN_+128) // 9344: +1 tile for lin columns
#define ML_ (B_*L_)   // 4096
#define BK 64
#define NC (H_/BK)    // 12
#define STG 32768u
#define SM_TOTAL (3*STG + 1024)

// Scratch (__device__ globals per allocation rules)
__device__ __nv_bfloat16 g_Xb[(size_t)ML_*H_];   // all rows (stage-2 B side)
__device__ __nv_bfloat16 g_Xc[(size_t)ML_*H_];   // globally compacted unmasked rows
__device__ __nv_bfloat16 g_W1t[(size_t)NT_*H_];  // rows 9216..9239 = wa^T, wb^T
__device__ __nv_bfloat16 g_Tb[(size_t)ML_*NN_];  // compacted T rows
__device__ float g_lini[ML_*O_];                 // only unmasked slots written; rest 0
__device__ float g_linj[ML_*O_];
__device__ int g_cnt[B_];
__device__ int g_off[B_ + 1];
__device__ int g_sgx[ML_];                       // b*L+j (compacted) -> original x
__device__ int g_inv[ML_];                       // global compacted r -> b*L+x

__device__ __forceinline__ uint32_t swz(uint32_t off){ return off ^ ((off>>3)&0x70); }
__device__ __forceinline__ void cp16(uint32_t saddr, const void* g){
    asm volatile("cp.async.cg.shared.global [%0], [%1], 16;\n" :: "r"(saddr), "l"(g));
}

#define LDM4(d0,d1,d2,d3,addr) \
  asm volatile("ldmatrix.sync.aligned.m8n8.x4.shared.b16 {%0,%1,%2,%3}, [%4];\n" \
    : "=r"(d0),"=r"(d1),"=r"(d2),"=r"(d3) : "r"(addr))

#define MMA16816(c,a0,a1,a2,a3,b0,b1) \
  asm volatile("mma.sync.aligned.m16n8k16.row.col.f32.bf16.bf16.f32 " \
    "{%0,%1,%2,%3}, {%4,%5,%6,%7}, {%8,%9}, {%0,%1,%2,%3};\n" \
    : "+f"(c[0]),"+f"(c[1]),"+f"(c[2]),"+f"(c[3]) \
    : "r"(a0),"r"(a1),"r"(a2),"r"(a3),"r"(b0),"r"(b1))

// ---------------------------------------------------------------------------
__global__ void conv_x(const float* __restrict__ X){
    int i = blockIdx.x*256 + threadIdx.x;
    float4 v = ((const float4*)X)[i];
    ((__nv_bfloat162*)g_Xb)[2*i]   = __floats2bfloat162_rn(v.x, v.y);
    ((__nv_bfloat162*)g_Xb)[2*i+1] = __floats2bfloat162_rn(v.z, v.w);
}

__global__ void conv_w1(const float* __restrict__ W1){
    __shared__ float t[32][33];
    int n0 = blockIdx.x*32, i0 = blockIdx.y*32;
    int tx = threadIdx.x, ty = threadIdx.y;        // (32, 8)
#pragma unroll
    for (int r = 0; r < 4; r++)
        t[ty+8*r][tx] = W1[(size_t)(i0+ty+8*r)*NN_ + n0+tx];
    __syncthreads();
#pragma unroll
    for (int r = 0; r < 4; r++)
        g_W1t[(size_t)(n0+ty+8*r)*H_ + i0+tx] = __float2bfloat16_rn(t[tx][ty+8*r]);
}

// wa^T / wb^T as rows 9216..9239 of W1t.
__global__ void conv_w2t(const float* __restrict__ W2){
    int op = blockIdx.x;                 // 0..23
    int row = NN_ + op;
    for (int k = threadIdx.x; k < H_; k += 256){
        float v = (op < O_) ? W2[k*O_ + op] : W2[(H_+k)*O_ + (op-O_)];
        g_W1t[(size_t)row*H_ + k] = __float2bfloat16_rn(v);
    }
}

// ---------------------------------------------------------------------------
__global__ void scan_kernel(const int* __restrict__ mask){
    __shared__ int wsum[16];
    int b = blockIdx.x, tid = threadIdx.x, lane = tid & 31, w = tid >> 5;
    int m = mask[b*L_ + tid];
    unsigned bal = __ballot_sync(0xFFFFFFFFu, m);
    int wpre = __popc(bal & ((1u << lane) - 1));
    if (lane == 31) wsum[w] = __popc(bal);
    __syncthreads();
    if (tid == 0){
        int s = 0;
#pragma unroll
        for (int i = 0; i < 16; i++){ int t = wsum[i]; wsum[i] = s; s += t; }
        g_cnt[b] = s;
    }
    __syncthreads();
    if (m) g_sgx[b*L_ + wsum[w] + wpre] = tid;
}

__global__ void offs_kernel(){
    int s = 0;
#pragma unroll
    for (int b = 0; b < B_; b++){ g_off[b] = s; s += g_cnt[b]; }
    g_off[B_] = s;
}

__global__ void gather_kernel(const float* __restrict__ X){
    int b = blockIdx.y;
    int cnt = g_cnt[b];
    int off = g_off[b];
    int j0 = blockIdx.x*16;
    int lane = threadIdx.x & 31, w = threadIdx.x >> 5;
#pragma unroll
    for (int it = 0; it < 2; it++){
        int j = j0 + it*8 + w;
        if (j >= cnt) continue;
        int x = g_sgx[b*L_ + j];
        if (lane == 0) g_inv[off + j] = b*L_ + x;
        const float* src = X + (size_t)(b*L_ + x)*H_;
        __nv_bfloat16* dst = g_Xc + (size_t)(off + j)*H_;
        for (int k = lane; k < H_/2; k += 32){
            float2 v = ((const float2*)src)[k];
            ((__nv_bfloat162*)dst)[k] = __floats2bfloat162_rn(v.x, v.y);
        }
    }
}

__global__ void fill_masked(const int* __restrict__ mask, float* __restrict__ out){
    int row = blockIdx.x;
    int b = row >> 9, x = row & 511;
    if (mask[row]) return;
    int t = threadIdx.x;
    float4 v;
    int y0 = t*4;
    v.x = (y0+0 < x) ? (-NEGC - NEGC) : -NEGC;
    v.y = (y0+1 < x) ? (-NEGC - NEGC) : -NEGC;
    v.z = (y0+2 < x) ? (-NEGC - NEGC) : -NEGC;
    v.w = (y0+3 < x) ? (-NEGC - NEGC) : -NEGC;
#pragma unroll
    for (int o = 0; o < O_; o++)
        *(float4*)&out[((size_t)(b*O_+o)*L_ + x)*L_ + y0] = v;
}

// ---------------------------------------------------------------------------
// STAGE 1: [Tb | lin] = Xc @ W1t^T over N=9344. Last N tile -> lini/linj.
// ---------------------------------------------------------------------------
__device__ __forceinline__ void s1_fill(uint32_t sb, int stg,
    const __nv_bfloat16* Agl, const __nv_bfloat16* Bgl, int kt, int lr, int lc)
{
    uint32_t ab = sb + (uint32_t)stg*STG, bb = ab + 16384u;
#pragma unroll
    for (int q = 0; q < 4; q++)
        cp16(ab + swz((lr+32*q)*128 + lc*16), Agl + (size_t)(32*q)*H_ + kt);
#pragma unroll
    for (int q = 0; q < 4; q++)
        cp16(bb + swz((lr+32*q)*128 + lc*16), Bgl + (size_t)(32*q)*H_ + kt);
    asm volatile("cp.async.commit_group;\n");
}

__global__ __launch_bounds__(256, 2) void s1_gemm()
{
    extern __shared__ __align__(1024) char smem[];
    uint32_t sb = (uint32_t)__cvta_generic_to_shared(smem);
    int tid = threadIdx.x, lane = tid & 31, warp = tid >> 5;
    int wm = warp >> 1, wn = warp & 1;

    int bm = blockIdx.y*128, bn = blockIdx.x*128;
    int tot = g_off[B_];
    if (bm >= tot) return;

    const __nv_bfloat16* Ag = g_Xc  + (size_t)bm*H_;
    const __nv_bfloat16* Bg = g_W1t + (size_t)bn*H_;
    int lr = tid >> 3, lc = tid & 7;
    const __nv_bfloat16* Agl = Ag + (size_t)lr*H_ + lc*8;
    const __nv_bfloat16* Bgl = Bg + (size_t)lr*H_ + lc*8;

    float acc[2][8][4];
#pragma unroll
    for (int i=0;i<2;i++) for (int j=0;j<8;j++) for (int k=0;k<4;k++) acc[i][j][k]=0.f;

    s1_fill(sb, 0, Agl, Bgl, 0,  lr, lc);
    s1_fill(sb, 1, Agl, Bgl, BK, lr, lc);

    int rsel = lane & 15, hi = lane >> 4;
    for (int c = 0; c < NC; c++){
        if (c + 1 < NC) asm volatile("cp.async.wait_group 1;\n");
        else            asm volatile("cp.async.wait_group 0;\n");
        __syncthreads();
        uint32_t ab = sb + (uint32_t)(c % 3)*STG, bb = ab + 16384u;
#pragma unroll
        for (int ks = 0; ks < 4; ks++){
            uint32_t a[2][4], bf[4][4];
#pragma unroll
            for (int mt = 0; mt < 2; mt++){
                uint32_t off = (wm*32 + mt*16 + rsel)*128 + ks*32 + hi*16;
                LDM4(a[mt][0],a[mt][1],a[mt][2],a[mt][3], ab + swz(off));
            }
#pragma unroll
            for (int p = 0; p < 4; p++){
                uint32_t off = (wn*64 + p*16 + rsel)*128 + ks*32 + hi*16;
                LDM4(bf[p][0],bf[p][1],bf[p][2],bf[p][3], bb + swz(off));
            }
#pragma unroll
            for (int mt = 0; mt < 2; mt++)
#pragma unroll
                for (int nt = 0; nt < 8; nt++)
                    MMA16816(acc[mt][nt], a[mt][0],a[mt][1],a[mt][2],a[mt][3],
                             bf[nt>>1][nt&1], bf[nt>>1][2+(nt&1)]);
        }
        if (c + 2 < NC)
            s1_fill(sb, (c + 2) % 3, Agl, Bgl, (c+2)*BK, lr, lc);
    }

    int g = lane >> 2, t2 = (lane & 3)*2;
    if (bn < NN_){
#pragma unroll
        for (int mt = 0; mt < 2; mt++){
            int row = bm + wm*32 + mt*16 + g;
#pragma unroll
            for (int nt = 0; nt < 8; nt++){
                int col = bn + wn*64 + nt*8 + t2;
                *(__nv_bfloat162*)&g_Tb[(size_t)row*NN_ + col] =
                    __floats2bfloat162_rn(acc[mt][nt][0], acc[mt][nt][1]);
                *(__nv_bfloat162*)&g_Tb[(size_t)(row+8)*NN_ + col] =
                    __floats2bfloat162_rn(acc[mt][nt][2], acc[mt][nt][3]);
            }
        }
    } else if (wn == 0){
        // lin tile: cols 0..11 = lin_i, 12..23 = lin_j (rest garbage, skip)
#pragma unroll
        for (int mt = 0; mt < 2; mt++)
#pragma unroll
            for (int half = 0; half < 2; half++){
                int row = bm + wm*32 + mt*16 + g + half*8;
                if (row >= tot) continue;
                int inv = g_inv[row];
#pragma unroll
                for (int nt = 0; nt < 3; nt++){
#pragma unroll
                    for (int e = 0; e < 2; e++){
                        int col = nt*8 + t2 + e;
                        float v = acc[mt][nt][half*2 + e];
                        if (col < O_)            g_lini[inv*O_ + col]        = v;
                        else if (col < 2*O_)     g_linj[inv*O_ + (col-O_)]   = v;
                    }
                }
            }
    }
}

// ---------------------------------------------------------------------------
// STAGE 2 (row-compacted, unchanged from round 13)
// ---------------------------------------------------------------------------
__device__ __forceinline__ void s2_fill(uint32_t sb, int stg,
    const __nv_bfloat16* Agl, const __nv_bfloat16* Bgl, int kt, int lr, int lc)
{
    uint32_t ab = sb + (uint32_t)stg*STG, bb = ab + 16384u;
#pragma unroll
    for (int q = 0; q < 4; q++)
        cp16(ab + swz((lr+32*q)*128 + lc*16), Agl + (size_t)(32*q)*NN_ + kt);
#pragma unroll
    for (int q = 0; q < 4; q++)
        cp16(bb + swz((lr+32*q)*128 + lc*16), Bgl + (size_t)(32*q)*H_ + kt);
    asm volatile("cp.async.commit_group;\n");
}

__global__ __launch_bounds__(256, 2) void s2_gemm(
    const float* __restrict__ W2, const int* __restrict__ mask, float* __restrict__ out)
{
    extern __shared__ __align__(1024) char smem[];
    uint32_t sb = (uint32_t)__cvta_generic_to_shared(smem);
    int tid = threadIdx.x, lane = tid & 31, warp = tid >> 5;
    int wm = warp >> 1, wn = warp & 1;

    int bo = blockIdx.z;
    int b = bo / O_, o = bo % O_;
    int bm = blockIdx.y*128, bn = blockIdx.x*128;
    int cnt = g_cnt[b];
    if (bm >= cnt) return;
    int nrow = min(128, cnt - bm);
    int x_min = g_sgx[b*L_ + bm];

    size_t outbase = (size_t)bo*L_*L_;

    if (bn + 128 <= x_min){
        for (int r = tid >> 1; r < nrow; r += 128){
            int x  = g_sgx[b*L_ + bm + r];
            int cb = (tid & 1)*64;
            const int* mrow = mask + b*L_ + bn + cb;
            float* orow = out + outbase + (size_t)x*L_ + bn + cb;
#pragma unroll
            for (int j = 0; j < 64; j += 4){
                float4 v;
                v.x = mrow[j+0] ? -NEGC : (-NEGC - NEGC);
                v.y = mrow[j+1] ? -NEGC : (-NEGC - NEGC);
                v.z = mrow[j+2] ? -NEGC : (-NEGC - NEGC);
                v.w = mrow[j+3] ? -NEGC : (-NEGC - NEGC);
                *(float4*)&orow[j] = v;
            }
        }
        return;
    }

    int* s_sgx = (int*)(smem + 3*STG);
    if (tid < 128)
        s_sgx[tid] = (tid < nrow) ? g_sgx[b*L_ + bm + tid] : -1;

    const __nv_bfloat16* Ag = g_Tb + (size_t)(g_off[b] + bm)*NN_ + o*H_;
    const __nv_bfloat16* Bg = g_Xb + (size_t)(b*L_ + bn)*H_;
    int lr = tid >> 3, lc = tid & 7;
    const __nv_bfloat16* Agl = Ag + (size_t)lr*NN_ + lc*8;
    const __nv_bfloat16* Bgl = Bg + (size_t)lr*H_ + lc*8;

    float acc[2][8][4];
#pragma unroll
    for (int i=0;i<2;i++) for (int j=0;j<8;j++) for (int k=0;k<4;k++) acc[i][j][k]=0.f;

    s2_fill(sb, 0, Agl, Bgl, 0,  lr, lc);
    s2_fill(sb, 1, Agl, Bgl, BK, lr, lc);

    int rsel = lane & 15, hi = lane >> 4;
    for (int c = 0; c < NC; c++){
        if (c + 1 < NC) asm volatile("cp.async.wait_group 1;\n");
        else            asm volatile("cp.async.wait_group 0;\n");
        __syncthreads();
        uint32_t ab = sb + (uint32_t)(c % 3)*STG, bb = ab + 16384u;
#pragma unroll
        for (int ks = 0; ks < 4; ks++){
            uint32_t a[2][4], bf[4][4];
#pragma unroll
            for (int mt = 0; mt < 2; mt++){
                uint32_t off = (wm*32 + mt*16 + rsel)*128 + ks*32 + hi*16;
                LDM4(a[mt][0],a[mt][1],a[mt][2],a[mt][3], ab + swz(off));
            }
#pragma unroll
            for (int p = 0; p < 4; p++){
                uint32_t off = (wn*64 + p*16 + rsel)*128 + ks*32 + hi*16;
                LDM4(bf[p][0],bf[p][1],bf[p][2],bf[p][3], bb + swz(off));
            }
#pragma unroll
            for (int mt = 0; mt < 2; mt++)
#pragma unroll
                for (int nt = 0; nt < 8; nt++)
                    MMA16816(acc[mt][nt], a[mt][0],a[mt][1],a[mt][2],a[mt][3],
                             bf[nt>>1][nt&1], bf[nt>>1][2+(nt&1)]);
        }
        if (c + 2 < NC)
            s2_fill(sb, (c + 2) % 3, Agl, Bgl, (c+2)*BK, lr, lc);
    }

    int g = lane >> 2, t2 = (lane & 3)*2;
    float bias = W2[2*H_*O_ + o];
    int myv[16]; float lj[16];
#pragma unroll
    for (int nt = 0; nt < 8; nt++){
        int y = bn + wn*64 + nt*8 + t2;
        myv[2*nt]   = mask[b*L_+y];
        myv[2*nt+1] = mask[b*L_+y+1];
        lj[2*nt]    = g_linj[(b*L_+y)*O_+o];
        lj[2*nt+1]  = g_linj[(b*L_+y+1)*O_+o];
    }
#pragma unroll
    for (int mt = 0; mt < 2; mt++)
#pragma unroll
        for (int half = 0; half < 2; half++){
            int rloc = wm*32 + mt*16 + g + half*8;
            int x = s_sgx[rloc];
            if (x < 0) continue;
            float li = g_lini[(b*L_+x)*O_+o] + bias;
            float* orow = out + outbase + (size_t)x*L_;
#pragma unroll
            for (int nt = 0; nt < 8; nt++){
                int y = bn + wn*64 + nt*8 + t2;
                float v0 = acc[mt][nt][half*2+0] + li + lj[2*nt];
                float v1 = acc[mt][nt][half*2+1] + li + lj[2*nt+1];
                if (!myv[2*nt])    v0 = -NEGC;
                if (!myv[2*nt+1])  v1 = -NEGC;
                if (y   < x)       v0 -= NEGC;
                if (y+1 < x)       v1 -= NEGC;
                *(float2*)&orow[y] = make_float2(v0, v1);
            }
        }
}

// ---------------------------------------------------------------------------
extern "C" void kernel_launch(void* const* d_in, const int* in_sizes, int n_in,
                              void* d_out, int out_size) {
    const float* inputs = nullptr;
    const float* w1 = nullptr;
    const float* w2 = nullptr;
    const int*   mask = nullptr;
    for (int i = 0; i < n_in; i++) {
        if      (in_sizes[i] == B_*L_*H_)      inputs = (const float*)d_in[i];
        else if (in_sizes[i] == H_*O_*H_)      w1     = (const float*)d_in[i];
        else if (in_sizes[i] == (2*H_+1)*O_)   w2     = (const float*)d_in[i];
        else if (in_sizes[i] == B_*L_)         mask   = (const int*)d_in[i];
    }
    float* out = (float*)d_out;

    cudaFuncSetAttribute(s1_gemm, cudaFuncAttributeMaxDynamicSharedMemorySize, SM_TOTAL);
    cudaFuncSetAttribute(s2_gemm, cudaFuncAttributeMaxDynamicSharedMemorySize, SM_TOTAL);

    scan_kernel<<<B_, 512>>>(mask);
    offs_kernel<<<1, 1>>>();
    conv_x<<<(ML_*H_/4)/256, 256>>>(inputs);
    conv_w1<<<dim3(NN_/32, H_/32), dim3(32,8)>>>(w1);
    conv_w2t<<<24, 256>>>(w2);
    gather_kernel<<<dim3(32, B_), 256>>>(inputs);
    fill_masked<<<ML_, 128>>>(mask, out);
    s1_gemm<<<dim3(NT_/128, ML_/128), 256, SM_TOTAL>>>();
    s2_gemm<<<dim3(L_/128, L_/128, B_*O_), 256, SM_TOTAL>>>(w2, mask, out);
}